// round 8
// baseline (speedup 1.0000x reference)
#include <cuda_runtime.h>

#define NUM_NET 2
#define V 100000
#define D 128
#define B 4096
#define K 5
#define NS 10

#define NTHREADS 256
#define WPB 8
#define NEIGH_WARPS (NUM_NET * B * 4)   // 32768: 4 warps per (i,b) on neigh tables
#define NODE_WARPS  (NUM_NET * B)       // 8192:  1 warp per (i,b) on node tables
#define TOT_WARPS (NEIGH_WARPS + NODE_WARPS)
#define NBLOCKS (TOT_WARPS / WPB)       // 5120

__device__ float g_part[NBLOCKS];
__device__ int   g_count = 0;

__device__ __forceinline__ float logsig_fast(float x) {
    // log(sigmoid(x)) = min(x,0) - log(1 + exp(-|x|)); fast-math (err ~1e-6 vs 1e-3 budget)
    return fminf(x, 0.0f) - __logf(1.0f + __expf(-fabsf(x)));
}

__device__ __forceinline__ float dot4(float4 a, float4 b) {
    return fmaf(a.x, b.x, fmaf(a.y, b.y, fmaf(a.z, b.z, a.w * b.w)));
}

__device__ __forceinline__ void load5(float4 (&c)[5], const float* __restrict__ tab,
                                      const int* __restrict__ idx, int lane) {
    #pragma unroll
    for (int u = 0; u < 5; u++) {
        int id = __ldg(idx + u);
        c[u] = __ldg(reinterpret_cast<const float4*>(tab + (size_t)id * D) + lane);
    }
}

// Software-pipelined: dots free the row registers, next batch's loads issue
// BEFORE the shuffle-reduce + logsig of the current batch, so ~150 cyc of
// reduce work overlaps every load batch. M = runtime multiple of 5.
template<bool NEG>
__device__ __forceinline__ float rows_pipe5(const float* __restrict__ tab,
                                            const int* __restrict__ idx,
                                            int M, float4 ne, int lane) {
    float a = 0.0f;
    float4 c[5];
    load5(c, tab, idx, lane);
    for (int m = 5; m <= M; m += 5) {
        float s[5];
        #pragma unroll
        for (int u = 0; u < 5; u++) s[u] = dot4(ne, c[u]);   // frees c
        if (m < M) load5(c, tab, idx + m, lane);             // issue next batch now
        #pragma unroll
        for (int off = 16; off; off >>= 1) {
            #pragma unroll
            for (int u = 0; u < 5; u++)
                s[u] += __shfl_xor_sync(0xffffffffu, s[u], off);
        }
        #pragma unroll
        for (int u = 0; u < 5; u++) a += logsig_fast(NEG ? -s[u] : s[u]);
    }
    return a;
}

// Three single-row positive terms from three (table, index) pairs, batched.
__device__ __forceinline__ float pos3(const float* __restrict__ t0, int i0,
                                      const float* __restrict__ t1, int i1,
                                      const float* __restrict__ t2, int i2,
                                      float4 ne, int lane) {
    float4 c0 = __ldg(reinterpret_cast<const float4*>(t0 + (size_t)i0 * D) + lane);
    float4 c1 = __ldg(reinterpret_cast<const float4*>(t1 + (size_t)i1 * D) + lane);
    float4 c2 = __ldg(reinterpret_cast<const float4*>(t2 + (size_t)i2 * D) + lane);
    float s0 = dot4(ne, c0), s1 = dot4(ne, c1), s2 = dot4(ne, c2);
    #pragma unroll
    for (int off = 16; off; off >>= 1) {
        s0 += __shfl_xor_sync(0xffffffffu, s0, off);
        s1 += __shfl_xor_sync(0xffffffffu, s1, off);
        s2 += __shfl_xor_sync(0xffffffffu, s2, off);
    }
    return logsig_fast(s0) + logsig_fast(s1) + logsig_fast(s2);
}

__global__ void __launch_bounds__(NTHREADS, 6)
loss_kernel(const float* __restrict__ node_tables,
            const float* __restrict__ neigh_tables,
            const int* __restrict__ nodes_idx,
            const int* __restrict__ neigh_idx,
            const int* __restrict__ role_idx,
            const int* __restrict__ neg_main,
            const int* __restrict__ neg_node,
            const int* __restrict__ neg_cross,
            const int* __restrict__ neg_role,
            float* __restrict__ out) {
    const int lane = threadIdx.x & 31;
    const int wid  = threadIdx.x >> 5;
    const int gw   = blockIdx.x * WPB + wid;
    const size_t VD = (size_t)V * D;

    const float CB = 1.0f / (10.0f * (float)B);
    const float WH = 0.1f;

    float acc = 0.0f;

    if (gw < NEIGH_WARPS) {
        // ---- phase 1: neigh-table terms (t1, t3); L2 holds the two neigh tables ----
        const int pair = gw >> 2;
        const int sub  = gw & 3;
        const int i = pair / B;
        const int b = pair % B;
        const int j = 1 - i;

        const float* gt_i = neigh_tables + (size_t)i * VD;
        const float* gt_j = neigh_tables + (size_t)j * VD;

        const int nid = __ldg(nodes_idx + i * B + b);
        const float4 ne = __ldg(reinterpret_cast<const float4*>(
            node_tables + (size_t)i * VD + (size_t)nid * D) + lane);

        const int* nm = neg_main  + (size_t)(i * B + b) * (K * NS);
        const int* nc = neg_cross + (size_t)((i * NUM_NET + j) * B + b) * (K * NS);

        if (sub == 0) {
            // t1 pos (5) + neg_main[0:25]   -> 30 rows
            acc += rows_pipe5<false>(gt_i, neigh_idx + (i * B + b) * K, K, ne, lane) * (-CB / (float)K);
            acc += rows_pipe5<true>(gt_i, nm, 25, ne, lane) * (-CB);
        } else if (sub == 1) {
            // neg_main[25:50] + t3 pos (5)  -> 30 rows
            acc += rows_pipe5<true>(gt_i, nm + 25, 25, ne, lane) * (-CB);
            acc += rows_pipe5<false>(gt_j, neigh_idx + (i * B + b) * K, K, ne, lane) * (-WH * CB / (float)K);
        } else if (sub == 2) {
            acc += rows_pipe5<true>(gt_j, nc, 25, ne, lane) * (-WH * CB);
        } else {
            acc += rows_pipe5<true>(gt_j, nc + 25, 25, ne, lane) * (-WH * CB);
        }
    } else {
        // ---- phase 2: node-table terms (t2, roles); runs in the last wave ----
        const int pair = gw - NEIGH_WARPS;
        const int i = pair / B;
        const int b = pair % B;
        const int j = 1 - i;

        const float* nt_j = node_tables + (size_t)j * VD;

        const int nid = __ldg(nodes_idx + i * B + b);
        const float4 ne = __ldg(reinterpret_cast<const float4*>(
            node_tables + (size_t)i * VD + (size_t)nid * D) + lane);

        // three positives batched: t2 pos + role(j2=0) pos + role(j2=1) pos
        acc += pos3(nt_j, nid,
                    node_tables,      __ldg(role_idx + (i * NUM_NET + 0) * B + b),
                    node_tables + VD, __ldg(role_idx + (i * NUM_NET + 1) * B + b),
                    ne, lane) * (-WH * CB);
        // negatives: 3 x 10 rows, pipelined
        acc += rows_pipe5<true>(nt_j, neg_node + (size_t)((i * NUM_NET + j) * B + b) * NS, NS, ne, lane) * (-WH * CB);
        acc += rows_pipe5<true>(node_tables,      neg_role + (size_t)((i * NUM_NET + 0) * B + b) * NS, NS, ne, lane) * (-WH * CB);
        acc += rows_pipe5<true>(node_tables + VD, neg_role + (size_t)((i * NUM_NET + 1) * B + b) * NS, NS, ne, lane) * (-WH * CB);
    }

    __shared__ float sacc[WPB];
    __shared__ int s_last;
    if (lane == 0) sacc[wid] = acc;
    __syncthreads();
    if (threadIdx.x == 0) {
        float t = 0.0f;
        #pragma unroll
        for (int w = 0; w < WPB; w++) t += sacc[w];
        g_part[blockIdx.x] = t;       // always written: no zero-init needed
        __threadfence();
        int c = atomicAdd(&g_count, 1);
        s_last = (c == NBLOCKS - 1);
    }
    __syncthreads();

    // the last block to arrive reduces all partials; fixed read order -> deterministic
    if (s_last) {
        __threadfence();              // acquire: see all g_part writes
        __shared__ double sh[WPB];
        double t = 0.0;
        for (int k2 = threadIdx.x; k2 < NBLOCKS; k2 += NTHREADS)
            t += (double)g_part[k2];
        #pragma unroll
        for (int off = 16; off; off >>= 1)
            t += __shfl_xor_sync(0xffffffffu, t, off);
        if (lane == 0) sh[wid] = t;
        __syncthreads();
        if (threadIdx.x == 0) {
            double v = 0.0;
            #pragma unroll
            for (int w = 0; w < WPB; w++) v += sh[w];
            out[0] = (float)v;
            g_count = 0;              // reset for next graph replay
        }
    }
}

extern "C" void kernel_launch(void* const* d_in, const int* in_sizes, int n_in,
                              void* d_out, int out_size) {
    const float* node_tables  = (const float*)d_in[0];
    const float* neigh_tables = (const float*)d_in[1];
    const int*   nodes_idx    = (const int*)d_in[2];
    const int*   neigh_idx    = (const int*)d_in[3];
    const int*   role_idx     = (const int*)d_in[4];
    const int*   neg_main     = (const int*)d_in[5];
    const int*   neg_node     = (const int*)d_in[6];
    const int*   neg_cross    = (const int*)d_in[7];
    const int*   neg_role     = (const int*)d_in[8];

    (void)in_sizes; (void)n_in; (void)out_size;

    loss_kernel<<<NBLOCKS, NTHREADS>>>(node_tables, neigh_tables, nodes_idx,
                                       neigh_idx, role_idx, neg_main,
                                       neg_node, neg_cross, neg_role,
                                       (float*)d_out);
}

// round 9
// speedup vs baseline: 1.3229x; 1.3229x over previous
#include <cuda_runtime.h>

#define NUM_NET 2
#define V 100000
#define D 128
#define B 4096
#define K 5
#define NS 10

#define NTHREADS 256
#define WPB 8
// phase layout (block-index ordered => one 51MB table resident in L2 per phase):
//   [0, 16384)        : gt0 gathers  (t1 i=0, t3 i=1)
//   [16384, 32768)    : gt1 gathers  (t1 i=1, t3 i=0)
//   [32768, 40960)    : nt0 gathers  (t2/roles reading node table 0)
//   [40960, 49152)    : nt1 gathers
#define NEIGH_WARPS 32768
#define NODE_WARPS  16384
#define TOT_WARPS (NEIGH_WARPS + NODE_WARPS)
#define NBLOCKS (TOT_WARPS / WPB)       // 6144

__device__ float g_part[NBLOCKS];
__device__ int   g_count = 0;

__device__ __forceinline__ float logsig_fast(float x) {
    // log(sigmoid(x)) = min(x,0) - log(1 + exp(-|x|)); fast-math (err ~1e-6 vs 1e-3 budget)
    return fminf(x, 0.0f) - __logf(1.0f + __expf(-fabsf(x)));
}

__device__ __forceinline__ float dot4(float4 a, float4 b) {
    return fmaf(a.x, b.x, fmaf(a.y, b.y, fmaf(a.z, b.z, a.w * b.w)));
}

// Sum of logsig(sign*(row . ne)) over M rows, 5 independent chains per batch.
// EXACT R6 shape: compiles to 32 regs -> 64 warps/SM. Do not touch.
template<bool NEG>
__device__ __forceinline__ float rows_sum5(const float* __restrict__ tab,
                                           const int* __restrict__ idx,
                                           int M, float4 ne, int lane) {
    float a = 0.0f;
    for (int m = 0; m < M; m += 5) {
        float4 c[5];
        #pragma unroll
        for (int u = 0; u < 5; u++) {
            int id = __ldg(idx + m + u);
            c[u] = __ldg(reinterpret_cast<const float4*>(tab + (size_t)id * D) + lane);
        }
        float s[5];
        #pragma unroll
        for (int u = 0; u < 5; u++) s[u] = dot4(ne, c[u]);
        #pragma unroll
        for (int off = 16; off; off >>= 1) {
            #pragma unroll
            for (int u = 0; u < 5; u++)
                s[u] += __shfl_xor_sync(0xffffffffu, s[u], off);
        }
        #pragma unroll
        for (int u = 0; u < 5; u++) a += logsig_fast(NEG ? -s[u] : s[u]);
    }
    return a;
}

// Two single positive rows from the same table, batched.
__device__ __forceinline__ float pos2(const float* __restrict__ tab, int i0, int i1,
                                      float4 ne, int lane) {
    float4 c0 = __ldg(reinterpret_cast<const float4*>(tab + (size_t)i0 * D) + lane);
    float4 c1 = __ldg(reinterpret_cast<const float4*>(tab + (size_t)i1 * D) + lane);
    float s0 = dot4(ne, c0), s1 = dot4(ne, c1);
    #pragma unroll
    for (int off = 16; off; off >>= 1) {
        s0 += __shfl_xor_sync(0xffffffffu, s0, off);
        s1 += __shfl_xor_sync(0xffffffffu, s1, off);
    }
    return logsig_fast(s0) + logsig_fast(s1);
}

__device__ __forceinline__ float pos1(const float* __restrict__ tab, int i0,
                                      float4 ne, int lane) {
    float4 c0 = __ldg(reinterpret_cast<const float4*>(tab + (size_t)i0 * D) + lane);
    float s0 = dot4(ne, c0);
    #pragma unroll
    for (int off = 16; off; off >>= 1)
        s0 += __shfl_xor_sync(0xffffffffu, s0, off);
    return logsig_fast(s0);
}

__global__ void __launch_bounds__(NTHREADS)
loss_kernel(const float* __restrict__ node_tables,
            const float* __restrict__ neigh_tables,
            const int* __restrict__ nodes_idx,
            const int* __restrict__ neigh_idx,
            const int* __restrict__ role_idx,
            const int* __restrict__ neg_main,
            const int* __restrict__ neg_node,
            const int* __restrict__ neg_cross,
            const int* __restrict__ neg_role,
            float* __restrict__ out) {
    const int lane = threadIdx.x & 31;
    const int wid  = threadIdx.x >> 5;
    const int gw   = blockIdx.x * WPB + wid;
    const size_t VD = (size_t)V * D;

    const float CB = 1.0f / (10.0f * (float)B);
    const float WH = 0.1f;

    float acc = 0.0f;

    if (gw < NEIGH_WARPS) {
        // ---- neigh-table phases: all gathers hit table gt_g only ----
        const int g   = gw >> 14;          // target neigh table
        const int r   = gw & 16383;
        const int b   = r >> 2;
        const int sub = r & 3;

        const float* gt = neigh_tables + (size_t)g * VD;

        if (sub < 2) {
            // term A: main SGNS of view i=g (weight 1)
            const int nid = __ldg(nodes_idx + g * B + b);
            const float4 ne = __ldg(reinterpret_cast<const float4*>(
                node_tables + (size_t)g * VD + (size_t)nid * D) + lane);
            const int* nm = neg_main + (size_t)(g * B + b) * (K * NS);
            if (sub == 0) {
                acc += rows_sum5<false>(gt, neigh_idx + (g * B + b) * K, K, ne, lane) * (-CB / (float)K);
                acc += rows_sum5<true>(gt, nm, 25, ne, lane) * (-CB);
            } else {
                acc += rows_sum5<true>(gt, nm + 25, 25, ne, lane) * (-CB);
            }
        } else {
            // term B: cross neighbor loss of view i=1-g with j=g (weight HYP2)
            const int i = 1 - g;
            const int nid = __ldg(nodes_idx + i * B + b);
            const float4 ne = __ldg(reinterpret_cast<const float4*>(
                node_tables + (size_t)i * VD + (size_t)nid * D) + lane);
            const int* nc = neg_cross + (size_t)((i * NUM_NET + g) * B + b) * (K * NS);
            if (sub == 2) {
                acc += rows_sum5<false>(gt, neigh_idx + (i * B + b) * K, K, ne, lane) * (-WH * CB / (float)K);
                acc += rows_sum5<true>(gt, nc, 25, ne, lane) * (-WH * CB);
            } else {
                acc += rows_sum5<true>(gt, nc + 25, 25, ne, lane) * (-WH * CB);
            }
        }
    } else {
        // ---- node-table phases: all gathers hit node table nt_m only ----
        const int w2 = gw - NEIGH_WARPS;   // 0 .. 16383
        const int m  = w2 >> 13;           // target node table
        const int r  = w2 & 8191;
        const int i  = r >> 12;            // owning view (ne source)
        const int b  = r & 4095;

        const float* nt = node_tables + (size_t)m * VD;

        const int nid = __ldg(nodes_idx + i * B + b);
        const float4 ne = __ldg(reinterpret_cast<const float4*>(
            node_tables + (size_t)i * VD + (size_t)nid * D) + lane);

        const float w = -WH * CB;
        const int* nr = neg_role + (size_t)((i * NUM_NET + m) * B + b) * NS;
        const int rp  = __ldg(role_idx + (i * NUM_NET + m) * B + b);

        if (m != i) {
            // t2 (pos=nid row in nt_m, 10 negs) + role j2=m (pos + 10 negs): 22 rows
            acc += pos2(nt, nid, rp, ne, lane) * w;
            acc += rows_sum5<true>(nt, neg_node + (size_t)((i * NUM_NET + m) * B + b) * NS, NS, ne, lane) * w;
            acc += rows_sum5<true>(nt, nr, NS, ne, lane) * w;
        } else {
            // role j2=m=i only: 11 rows
            acc += pos1(nt, rp, ne, lane) * w;
            acc += rows_sum5<true>(nt, nr, NS, ne, lane) * w;
        }
    }

    __shared__ float sacc[WPB];
    __shared__ int s_last;
    if (lane == 0) sacc[wid] = acc;
    __syncthreads();
    if (threadIdx.x == 0) {
        float t = 0.0f;
        #pragma unroll
        for (int w = 0; w < WPB; w++) t += sacc[w];
        g_part[blockIdx.x] = t;       // always written: no zero-init needed
        __threadfence();
        int c = atomicAdd(&g_count, 1);
        s_last = (c == NBLOCKS - 1);
    }
    __syncthreads();

    // the last block to arrive reduces all partials; fixed read order -> deterministic
    if (s_last) {
        __threadfence();              // acquire: see all g_part writes
        __shared__ double sh[WPB];
        double t = 0.0;
        for (int k2 = threadIdx.x; k2 < NBLOCKS; k2 += NTHREADS)
            t += (double)g_part[k2];
        #pragma unroll
        for (int off = 16; off; off >>= 1)
            t += __shfl_xor_sync(0xffffffffu, t, off);
        if (lane == 0) sh[wid] = t;
        __syncthreads();
        if (threadIdx.x == 0) {
            double v = 0.0;
            #pragma unroll
            for (int w = 0; w < WPB; w++) v += sh[w];
            out[0] = (float)v;
            g_count = 0;              // reset for next graph replay
        }
    }
}

extern "C" void kernel_launch(void* const* d_in, const int* in_sizes, int n_in,
                              void* d_out, int out_size) {
    const float* node_tables  = (const float*)d_in[0];
    const float* neigh_tables = (const float*)d_in[1];
    const int*   nodes_idx    = (const int*)d_in[2];
    const int*   neigh_idx    = (const int*)d_in[3];
    const int*   role_idx     = (const int*)d_in[4];
    const int*   neg_main     = (const int*)d_in[5];
    const int*   neg_node     = (const int*)d_in[6];
    const int*   neg_cross    = (const int*)d_in[7];
    const int*   neg_role     = (const int*)d_in[8];

    (void)in_sizes; (void)n_in; (void)out_size;

    loss_kernel<<<NBLOCKS, NTHREADS>>>(node_tables, neigh_tables, nodes_idx,
                                       neigh_idx, role_idx, neg_main,
                                       neg_node, neg_cross, neg_role,
                                       (float*)d_out);
}

// round 10
// speedup vs baseline: 1.3938x; 1.0536x over previous
#include <cuda_runtime.h>

#define NUM_NET 2
#define V 100000
#define D 128
#define B 4096
#define K 5
#define NS 10

#define NTHREADS 256
#define WPB 8
#define NEIGH_WARPS 32768               // 4 warps per (i,b), single-table phased
#define NODE_WARPS  16384               // 1 warp per (i,b,m)
#define NEIGH_BLOCKS (NEIGH_WARPS / WPB)   // 4096
#define NODE_BLOCKS  (NODE_WARPS / WPB)    // 2048
#define NPART (NEIGH_BLOCKS + NODE_BLOCKS) // 6144

__device__ float g_part[NPART];
__device__ int   g_count = 0;

__device__ __forceinline__ float logsig_fast(float x) {
    // log(sigmoid(x)) = min(x,0) - log(1 + exp(-|x|)); fast-math (err ~1e-6 vs 1e-3 budget)
    return fminf(x, 0.0f) - __logf(1.0f + __expf(-fabsf(x)));
}

__device__ __forceinline__ float dot4(float4 a, float4 b) {
    return fmaf(a.x, b.x, fmaf(a.y, b.y, fmaf(a.z, b.z, a.w * b.w)));
}

// Sum of logsig(sign*(row . ne)) over M rows, 5 independent chains per batch.
// The proven 32-reg shape. Do not touch.
template<bool NEG>
__device__ __forceinline__ float rows_sum5(const float* __restrict__ tab,
                                           const int* __restrict__ idx,
                                           int M, float4 ne, int lane) {
    float a = 0.0f;
    for (int m = 0; m < M; m += 5) {
        float4 c[5];
        #pragma unroll
        for (int u = 0; u < 5; u++) {
            int id = __ldg(idx + m + u);
            c[u] = __ldg(reinterpret_cast<const float4*>(tab + (size_t)id * D) + lane);
        }
        float s[5];
        #pragma unroll
        for (int u = 0; u < 5; u++) s[u] = dot4(ne, c[u]);
        #pragma unroll
        for (int off = 16; off; off >>= 1) {
            #pragma unroll
            for (int u = 0; u < 5; u++)
                s[u] += __shfl_xor_sync(0xffffffffu, s[u], off);
        }
        #pragma unroll
        for (int u = 0; u < 5; u++) a += logsig_fast(NEG ? -s[u] : s[u]);
    }
    return a;
}

__device__ __forceinline__ float pos2(const float* __restrict__ tab, int i0, int i1,
                                      float4 ne, int lane) {
    float4 c0 = __ldg(reinterpret_cast<const float4*>(tab + (size_t)i0 * D) + lane);
    float4 c1 = __ldg(reinterpret_cast<const float4*>(tab + (size_t)i1 * D) + lane);
    float s0 = dot4(ne, c0), s1 = dot4(ne, c1);
    #pragma unroll
    for (int off = 16; off; off >>= 1) {
        s0 += __shfl_xor_sync(0xffffffffu, s0, off);
        s1 += __shfl_xor_sync(0xffffffffu, s1, off);
    }
    return logsig_fast(s0) + logsig_fast(s1);
}

__device__ __forceinline__ float pos1(const float* __restrict__ tab, int i0,
                                      float4 ne, int lane) {
    float4 c0 = __ldg(reinterpret_cast<const float4*>(tab + (size_t)i0 * D) + lane);
    float s0 = dot4(ne, c0);
    #pragma unroll
    for (int off = 16; off; off >>= 1)
        s0 += __shfl_xor_sync(0xffffffffu, s0, off);
    return logsig_fast(s0);
}

__device__ __forceinline__ void block_publish(float acc, int lane, int wid, int slot) {
    __shared__ float sacc[WPB];
    if (lane == 0) sacc[wid] = acc;
    __syncthreads();
    if (threadIdx.x == 0) {
        float t = 0.0f;
        #pragma unroll
        for (int w = 0; w < WPB; w++) t += sacc[w];
        g_part[slot] = t;
    }
}

// ---------------- kernel 1: neigh-table terms (t1, t3) ----------------
__global__ void __launch_bounds__(NTHREADS)
neigh_kernel(const float* __restrict__ node_tables,
             const float* __restrict__ neigh_tables,
             const int* __restrict__ nodes_idx,
             const int* __restrict__ neigh_idx,
             const int* __restrict__ neg_main,
             const int* __restrict__ neg_cross) {
    const int lane = threadIdx.x & 31;
    const int wid  = threadIdx.x >> 5;
    const int gw   = blockIdx.x * WPB + wid;
    const size_t VD = (size_t)V * D;

    const float CB = 1.0f / (10.0f * (float)B);
    const float WH = 0.1f;

    // block-index ordered: first half targets gt0, second half gt1 -> one
    // 51MB table L2-resident per phase
    const int g   = gw >> 14;
    const int r   = gw & 16383;
    const int b   = r >> 2;
    const int sub = r & 3;

    const float* gt = neigh_tables + (size_t)g * VD;

    float acc = 0.0f;
    if (sub < 2) {
        // main SGNS of view i=g (weight 1)
        const int nid = __ldg(nodes_idx + g * B + b);
        const float4 ne = __ldg(reinterpret_cast<const float4*>(
            node_tables + (size_t)g * VD + (size_t)nid * D) + lane);
        const int* nm = neg_main + (size_t)(g * B + b) * (K * NS);
        if (sub == 0) {
            acc += rows_sum5<false>(gt, neigh_idx + (g * B + b) * K, K, ne, lane) * (-CB / (float)K);
            acc += rows_sum5<true>(gt, nm, 25, ne, lane) * (-CB);
        } else {
            acc += rows_sum5<true>(gt, nm + 25, 25, ne, lane) * (-CB);
        }
    } else {
        // cross neighbor loss of view i=1-g with j=g (weight HYP2)
        const int i = 1 - g;
        const int nid = __ldg(nodes_idx + i * B + b);
        const float4 ne = __ldg(reinterpret_cast<const float4*>(
            node_tables + (size_t)i * VD + (size_t)nid * D) + lane);
        const int* nc = neg_cross + (size_t)((i * NUM_NET + g) * B + b) * (K * NS);
        if (sub == 2) {
            acc += rows_sum5<false>(gt, neigh_idx + (i * B + b) * K, K, ne, lane) * (-WH * CB / (float)K);
            acc += rows_sum5<true>(gt, nc, 25, ne, lane) * (-WH * CB);
        } else {
            acc += rows_sum5<true>(gt, nc + 25, 25, ne, lane) * (-WH * CB);
        }
    }

    block_publish(acc, lane, wid, blockIdx.x);
}

// -------- kernel 2: node-table terms (t2, roles) + final reduction --------
__global__ void __launch_bounds__(NTHREADS)
node_kernel(const float* __restrict__ node_tables,
            const int* __restrict__ nodes_idx,
            const int* __restrict__ role_idx,
            const int* __restrict__ neg_node,
            const int* __restrict__ neg_role,
            float* __restrict__ out) {
    const int lane = threadIdx.x & 31;
    const int wid  = threadIdx.x >> 5;
    const int gw   = blockIdx.x * WPB + wid;
    const size_t VD = (size_t)V * D;

    const float CB = 1.0f / (10.0f * (float)B);
    const float WH = 0.1f;

    // block-index ordered by target node table m
    const int m = gw >> 13;
    const int r = gw & 8191;
    const int i = r >> 12;
    const int b = r & 4095;

    const float* nt = node_tables + (size_t)m * VD;

    const int nid = __ldg(nodes_idx + i * B + b);
    const float4 ne = __ldg(reinterpret_cast<const float4*>(
        node_tables + (size_t)i * VD + (size_t)nid * D) + lane);

    const float w = -WH * CB;
    const int* nr = neg_role + (size_t)((i * NUM_NET + m) * B + b) * NS;
    const int rp  = __ldg(role_idx + (i * NUM_NET + m) * B + b);

    float acc = 0.0f;
    if (m != i) {
        // t2 (pos=nid row in nt_m, 10 negs) + role j2=m (pos + 10 negs)
        acc += pos2(nt, nid, rp, ne, lane) * w;
        acc += rows_sum5<true>(nt, neg_node + (size_t)((i * NUM_NET + m) * B + b) * NS, NS, ne, lane) * w;
        acc += rows_sum5<true>(nt, nr, NS, ne, lane) * w;
    } else {
        // role j2=m=i only
        acc += pos1(nt, rp, ne, lane) * w;
        acc += rows_sum5<true>(nt, nr, NS, ne, lane) * w;
    }

    block_publish(acc, lane, wid, NEIGH_BLOCKS + blockIdx.x);

    // last node-block reduces ALL partials (kernel-1 partials already globally
    // visible: kernel boundary). Fixed read order -> deterministic.
    __shared__ int s_last;
    if (threadIdx.x == 0) {
        __threadfence();
        int c = atomicAdd(&g_count, 1);
        s_last = (c == NODE_BLOCKS - 1);
    }
    __syncthreads();
    if (s_last) {
        __threadfence();
        __shared__ double sh[WPB];
        double t = 0.0;
        for (int k2 = threadIdx.x; k2 < NPART; k2 += NTHREADS)
            t += (double)g_part[k2];
        #pragma unroll
        for (int off = 16; off; off >>= 1)
            t += __shfl_xor_sync(0xffffffffu, t, off);
        if (lane == 0) sh[wid] = t;
        __syncthreads();
        if (threadIdx.x == 0) {
            double v = 0.0;
            #pragma unroll
            for (int ww = 0; ww < WPB; ww++) v += sh[ww];
            out[0] = (float)v;
            g_count = 0;              // reset for next graph replay
        }
    }
}

extern "C" void kernel_launch(void* const* d_in, const int* in_sizes, int n_in,
                              void* d_out, int out_size) {
    const float* node_tables  = (const float*)d_in[0];
    const float* neigh_tables = (const float*)d_in[1];
    const int*   nodes_idx    = (const int*)d_in[2];
    const int*   neigh_idx    = (const int*)d_in[3];
    const int*   role_idx     = (const int*)d_in[4];
    const int*   neg_main     = (const int*)d_in[5];
    const int*   neg_node     = (const int*)d_in[6];
    const int*   neg_cross    = (const int*)d_in[7];
    const int*   neg_role     = (const int*)d_in[8];

    (void)in_sizes; (void)n_in; (void)out_size;

    neigh_kernel<<<NEIGH_BLOCKS, NTHREADS>>>(node_tables, neigh_tables, nodes_idx,
                                             neigh_idx, neg_main, neg_cross);
    node_kernel<<<NODE_BLOCKS, NTHREADS>>>(node_tables, nodes_idx, role_idx,
                                           neg_node, neg_role, (float*)d_out);
}